// round 3
// baseline (speedup 1.0000x reference)
#include <cuda_runtime.h>

#define NN 200000
#define DD 16
#define KK 16
#define FF 33
#define GN_EPS 1e-5f
#define SLOPE 0.2f

// Ping-pong feature buffers (device globals: no allocation allowed)
__device__ float g_buf0[NN * DD];
__device__ float g_buf1[NN * DD];
__device__ int g_is64;

// Detect whether idx buffer is int64 or int32 (jax may silently downcast).
__global__ void detect_idx_kernel(const long long* __restrict__ p) {
    int ok = 1;
#pragma unroll 1
    for (int i = 0; i < 64; i++) {
        long long v = p[i];
        if (v < 0 || v >= NN) ok = 0;
    }
    g_is64 = ok;
}

__device__ __forceinline__ float leaky(float x) {
    // fmax + fma(0.2, fmin, .) : FMNMX on alu pipe + 1 FFMA-imm
    return fmaf(SLOPE, fminf(x, 0.0f), fmaxf(x, 0.0f));
}

__global__ __launch_bounds__(256) void layer_kernel(
    const float* __restrict__ in_feat,   // [NN, DD]
    const float* __restrict__ dists,     // [NN, KK]
    const void*  __restrict__ idxv,      // [NN, KK] int64 or int32
    const float* __restrict__ W1,        // [FF, FF]  (f-major)
    const float* __restrict__ b1,        // [FF]
    const float* __restrict__ W2,        // [FF, DD]
    const float* __restrict__ b2,        // [DD]
    const float* __restrict__ gnw,       // [DD]
    const float* __restrict__ gnb,       // [DD]
    float* __restrict__ out_feat)        // [NN, DD]
{
    // Transposed W1: sW1T[g][f] = W1[f][g]; rows padded to 36 floats (144B, 16B-aligned)
    __shared__ float sW1T[FF][36];
    __shared__ float sW2[FF][DD];
    __shared__ float sb1[FF];
    __shared__ float sb2[DD], sgnw[DD], sgnb[DD];

    for (int i = threadIdx.x; i < FF * FF; i += blockDim.x) {
        int f = i / FF, g = i % FF;
        sW1T[g][f] = W1[i];
    }
    for (int i = threadIdx.x; i < FF * DD; i += blockDim.x) {
        sW2[i / DD][i % DD] = W2[i];
    }
    if (threadIdx.x < FF) sb1[threadIdx.x] = b1[threadIdx.x];
    if (threadIdx.x < DD) {
        sb2[threadIdx.x]  = b2[threadIdx.x];
        sgnw[threadIdx.x] = gnw[threadIdx.x];
        sgnb[threadIdx.x] = gnb[threadIdx.x];
    }
    __syncthreads();

    int n = blockIdx.x * blockDim.x + threadIdx.x;
    if (n >= NN) return;

    const int is64 = g_is64;

    // Load self features
    float self_[DD];
    {
        const float4* p = reinterpret_cast<const float4*>(in_feat + (size_t)n * DD);
        float4 a = p[0], b = p[1], c = p[2], d = p[3];
        self_[0] = a.x;  self_[1] = a.y;  self_[2] = a.z;  self_[3] = a.w;
        self_[4] = b.x;  self_[5] = b.y;  self_[6] = b.z;  self_[7] = b.w;
        self_[8] = c.x;  self_[9] = c.y;  self_[10] = c.z; self_[11] = c.w;
        self_[12] = d.x; self_[13] = d.y; self_[14] = d.z; self_[15] = d.w;
    }

    // selfW1[g] = b1[g] + sum_d self[d] * W1[d][g]   (self block is k-invariant)
    float sw[FF];
#pragma unroll
    for (int g = 0; g < FF; g++) {
        const float4* wr = reinterpret_cast<const float4*>(&sW1T[g][0]);
        float4 w0 = wr[0], w1 = wr[1], w2 = wr[2], w3 = wr[3];
        float acc = sb1[g];
        acc += self_[0] * w0.x + self_[1] * w0.y + self_[2] * w0.z + self_[3] * w0.w;
        acc += self_[4] * w1.x + self_[5] * w1.y + self_[6] * w1.z + self_[7] * w1.w;
        acc += self_[8] * w2.x + self_[9] * w2.y + self_[10] * w2.z + self_[11] * w2.w;
        acc += self_[12] * w3.x + self_[13] * w3.y + self_[14] * w3.z + self_[15] * w3.w;
        sw[g] = acc;
    }

    // messages accumulator, init with K * b2 (b2 added once per k in reference)
    float msg[DD];
#pragma unroll
    for (int d = 0; d < DD; d++) msg[d] = (float)KK * sb2[d];

#pragma unroll 1
    for (int k = 0; k < KK; k++) {
        long long j;
        if (is64) j = reinterpret_cast<const long long*>(idxv)[(size_t)n * KK + k];
        else      j = (long long)reinterpret_cast<const int*>(idxv)[(size_t)n * KK + k];
        float dk = dists[(size_t)n * KK + k];

        float nb[DD];
        {
            const float4* p = reinterpret_cast<const float4*>(in_feat + (size_t)j * DD);
            float4 a = p[0], b = p[1], c = p[2], d = p[3];
            nb[0] = a.x;  nb[1] = a.y;  nb[2] = a.z;  nb[3] = a.w;
            nb[4] = b.x;  nb[5] = b.y;  nb[6] = b.z;  nb[7] = b.w;
            nb[8] = c.x;  nb[9] = c.y;  nb[10] = c.z; nb[11] = c.w;
            nb[12] = d.x; nb[13] = d.y; nb[14] = d.z; nb[15] = d.w;
        }

#pragma unroll
        for (int g = 0; g < FF; g++) {
            // h[g] = leaky(selfW1[g] + nb . W1[nb-block][g] + dist * W1[32][g])
            const float4* wr = reinterpret_cast<const float4*>(&sW1T[g][16]);
            float4 w0 = wr[0], w1 = wr[1], w2 = wr[2], w3 = wr[3];
            float acc = sw[g] + dk * sW1T[g][32];
            acc += nb[0] * w0.x + nb[1] * w0.y + nb[2] * w0.z + nb[3] * w0.w;
            acc += nb[4] * w1.x + nb[5] * w1.y + nb[6] * w1.z + nb[7] * w1.w;
            acc += nb[8] * w2.x + nb[9] * w2.y + nb[10] * w2.z + nb[11] * w2.w;
            acc += nb[12] * w3.x + nb[13] * w3.y + nb[14] * w3.z + nb[15] * w3.w;
            float hg = leaky(acc);

            // msg[d] += hg * W2[g][d]
            const float4* ar = reinterpret_cast<const float4*>(&sW2[g][0]);
            float4 a0 = ar[0], a1 = ar[1], a2 = ar[2], a3 = ar[3];
            msg[0]  += hg * a0.x; msg[1]  += hg * a0.y; msg[2]  += hg * a0.z; msg[3]  += hg * a0.w;
            msg[4]  += hg * a1.x; msg[5]  += hg * a1.y; msg[6]  += hg * a1.z; msg[7]  += hg * a1.w;
            msg[8]  += hg * a2.x; msg[9]  += hg * a2.y; msg[10] += hg * a2.z; msg[11] += hg * a2.w;
            msg[12] += hg * a3.x; msg[13] += hg * a3.y; msg[14] += hg * a3.z; msg[15] += hg * a3.w;
        }
    }

    // GroupNorm (2 groups of 8) + leaky + residual
    float o[DD];
#pragma unroll
    for (int grp = 0; grp < 2; grp++) {
        float mu = 0.0f, m2 = 0.0f;
#pragma unroll
        for (int t = 0; t < 8; t++) {
            float v = msg[grp * 8 + t];
            mu += v;
            m2 += v * v;
        }
        mu *= 0.125f;
        float var = m2 * 0.125f - mu * mu;
        float inv = rsqrtf(var + GN_EPS);
#pragma unroll
        for (int t = 0; t < 8; t++) {
            int d = grp * 8 + t;
            float xn = (msg[d] - mu) * inv;
            float y = xn * sgnw[d] + sgnb[d];
            o[d] = self_[d] + leaky(y);
        }
    }

    float4* op = reinterpret_cast<float4*>(out_feat + (size_t)n * DD);
    op[0] = make_float4(o[0], o[1], o[2], o[3]);
    op[1] = make_float4(o[4], o[5], o[6], o[7]);
    op[2] = make_float4(o[8], o[9], o[10], o[11]);
    op[3] = make_float4(o[12], o[13], o[14], o[15]);
}

extern "C" void kernel_launch(void* const* d_in, const int* in_sizes, int n_in,
                              void* d_out, int out_size) {
    const float* y     = (const float*)d_in[0];
    const float* dists = (const float*)d_in[1];
    const float* W1    = (const float*)d_in[2];
    const float* b1    = (const float*)d_in[3];
    const float* W2    = (const float*)d_in[4];
    const float* b2    = (const float*)d_in[5];
    const float* gnw   = (const float*)d_in[6];
    const float* gnb   = (const float*)d_in[7];
    const void*  idx   = (const void*)d_in[8];
    float* out = (float*)d_out;

    float *buf0, *buf1;
    cudaGetSymbolAddress((void**)&buf0, g_buf0);
    cudaGetSymbolAddress((void**)&buf1, g_buf1);

    detect_idx_kernel<<<1, 1>>>((const long long*)idx);

    int blocks = (NN + 255) / 256;
    layer_kernel<<<blocks, 256>>>(y,    dists, idx, W1,              b1,          W2,              b2,          gnw,          gnb,          buf0);
    layer_kernel<<<blocks, 256>>>(buf0, dists, idx, W1 + 1 * FF * FF, b1 + 1 * FF, W2 + 1 * FF * DD, b2 + 1 * DD, gnw + 1 * DD, gnb + 1 * DD, buf1);
    layer_kernel<<<blocks, 256>>>(buf1, dists, idx, W1 + 2 * FF * FF, b1 + 2 * FF, W2 + 2 * FF * DD, b2 + 2 * DD, gnw + 2 * DD, gnb + 2 * DD, out);
}